// round 3
// baseline (speedup 1.0000x reference)
#include <cuda_runtime.h>
#include <math.h>

// Problem shapes (fixed by the dataset)
#define HB 4
#define CB 19
#define HH 512
#define WW 512
#define HW (HH*WW)            // 262144 = 1<<18
#define NPH (HB*CB)           // 76 planes per mask set
#define NP (2*NPH)            // 152 total planes (pred + tgt)
#define TILE 32
#define HALOD 34
#define HSZ (HALOD*HALOD)     // 1156
#define SMEM_BYTES ((CB*HSZ + HSZ)*4)   // 92480 bytes

// ---------------- device scratch (static, no allocation) ----------------
__device__ int g_labels[NP*HW];          // union-find labels, ~160 MB
__device__ int g_counts[NP];             // component counts per plane
__device__ unsigned int g_cx1;           // count(pred_b & valid)
__device__ unsigned int g_cx1y1;         // count(pred_b & tgt_b & valid)
__device__ unsigned int g_cvalid;        // count(valid) over B,H,W
__device__ int g_is64;                   // target dtype flag

// ---------------- init: zero counters + detect target dtype -------------
__global__ void k_init(const int* __restrict__ tgt32){
    int tid = threadIdx.x;
    // if target is int64 (little-endian), every odd 32-bit word is 0
    int nz = 0;
    for (int j = tid; j < 1024; j += blockDim.x)
        nz |= (tgt32[2*j + 1] != 0);
    int any = __syncthreads_or(nz);
    if (tid == 0){
        g_is64 = (any == 0);
        g_cx1 = 0u; g_cx1y1 = 0u; g_cvalid = 0u;
    }
    if (tid < NP) g_counts[tid] = 0;
}

// ---------------- fused softmax + boundary + mask + CCL init ------------
__global__ void __launch_bounds__(256)
k_fused(const float* __restrict__ pred, const void* __restrict__ tgt){
    extern __shared__ float smem[];
    float* s  = smem;                       // [CB][HSZ] softmax values
    int*   ts = (int*)(smem + CB*HSZ);      // [HSZ] target labels (-1 = outside)

    const int b   = blockIdx.z;
    const int tx0 = blockIdx.x * TILE;
    const int ty0 = blockIdx.y * TILE;
    const int tid = threadIdx.x;
    const int is64 = g_is64;
    const long long* t64 = (const long long*)tgt;
    const int*       t32 = (const int*)tgt;

    // ---- phase 1: load halo tile, compute per-pixel softmax into smem ----
    for (int hp = tid; hp < HSZ; hp += 256){
        int hy = hp / HALOD;
        int hx = hp - hy * HALOD;
        int gx = tx0 + hx - 1, gy = ty0 + hy - 1;
        int t = -1;
        if (gx >= 0 && gx < WW && gy >= 0 && gy < HH){
            int pix = b*HW + gy*WW + gx;
            t = is64 ? (int)t64[pix] : t32[pix];
            const float* base = pred + (size_t)b*CB*HW + (size_t)gy*WW + gx;
            float v[CB];
            float m = -1e30f;
            #pragma unroll
            for (int c = 0; c < CB; c++){ v[c] = base[(size_t)c*HW]; m = fmaxf(m, v[c]); }
            float sum = 0.f;
            #pragma unroll
            for (int c = 0; c < CB; c++){ v[c] = expf(v[c] - m); sum += v[c]; }
            float inv = 1.f / sum;
            #pragma unroll
            for (int c = 0; c < CB; c++) s[c*HSZ + hp] = v[c] * inv;
        } else {
            #pragma unroll
            for (int c = 0; c < CB; c++) s[c*HSZ + hp] = 0.f;
        }
        ts[hp] = t;
    }
    __syncthreads();

    // ---- phase 2: boundary counts + mask label init ----
    unsigned cx1 = 0, cx11 = 0, cval = 0;
    const int px  = tid & 31;
    const int py0 = tid >> 5;
    #pragma unroll
    for (int k = 0; k < 4; k++){
        int py = py0 + k*8;
        int gx = tx0 + px, gy = ty0 + py;
        int hc = (py+1)*HALOD + (px+1);
        int tc = ts[hc];
        bool valid = (tc != 255);
        cval += valid ? 1u : 0u;
        int n0 = ts[hc-HALOD-1], n1 = ts[hc-HALOD], n2 = ts[hc-HALOD+1];
        int n3 = ts[hc-1],                            n4 = ts[hc+1];
        int n5 = ts[hc+HALOD-1], n6 = ts[hc+HALOD],  n7 = ts[hc+HALOD+1];
        int pixoff = gy*WW + gx;
        int baseP  = b*CB*HW + pixoff;
        #pragma unroll
        for (int c = 0; c < CB; c++){
            const float* sc = s + c*HSZ;
            float ctr = sc[hc];
            float ns  = sc[hc-HALOD-1] + sc[hc-HALOD] + sc[hc-HALOD+1]
                      + sc[hc-1]       +                 sc[hc+1]
                      + sc[hc+HALOD-1] + sc[hc+HALOD] + sc[hc+HALOD+1];
            float lap = 8.f*ctr - ns;
            bool pb = fabsf(lap) > 0.1f;            // pred boundary
            int oc   = (tc == c) ? 1 : 0;           // one-hot (255/-1 never match)
            int osum = (n0==c)+(n1==c)+(n2==c)+(n3==c)+(n4==c)+(n5==c)+(n6==c)+(n7==c);
            bool tb = (8*oc != osum);               // tgt boundary (|int lap| > 0.1)
            bool x1 = pb && valid;
            cx1  += x1 ? 1u : 0u;
            cx11 += (x1 && tb) ? 1u : 0u;
            int gi = baseP + c*HW;
            g_labels[gi] = ((ctr > 0.5f) && valid) ? gi : -1;    // pred mask
            int gi2 = gi + NPH*HW;
            g_labels[gi2] = oc ? gi2 : -1;                       // tgt mask
        }
    }
    // warp reduce + per-warp atomics
    #pragma unroll
    for (int o = 16; o > 0; o >>= 1){
        cx1  += __shfl_down_sync(0xffffffffu, cx1,  o);
        cx11 += __shfl_down_sync(0xffffffffu, cx11, o);
        cval += __shfl_down_sync(0xffffffffu, cval, o);
    }
    if ((tid & 31) == 0){
        atomicAdd(&g_cx1,   cx1);
        atomicAdd(&g_cx1y1, cx11);
        atomicAdd(&g_cvalid, cval);
    }
}

// ---------------- union-find merge ----------------
__device__ __forceinline__ int find_root(int a){
    int p = g_labels[a];
    while (p != a){ a = p; p = g_labels[a]; }
    return a;
}

__device__ __forceinline__ void uf_merge(int i, int j){
    int a = find_root(i);
    int c = find_root(j);
    while (a != c){
        if (c < a){ int t = a; a = c; c = t; }   // a = min, c = max
        int old = atomicMin(&g_labels[c], a);
        if (old == c) break;                     // linked c -> a
        c = old;                                 // keep merging (old < c)
    }
}

__global__ void k_merge(){
    int i = blockIdx.x * 256 + threadIdx.x;
    int l = g_labels[i];
    if (l < 0) return;
    int x = i & (WW - 1);
    if (x > 0 && g_labels[i - 1]  >= 0) uf_merge(i, i - 1);
    int y = (i >> 9) & (HH - 1);
    if (y > 0 && g_labels[i - WW] >= 0) uf_merge(i, i - WW);
}

// ---------------- count roots per plane ----------------
__global__ void k_count(){
    __shared__ int sc;
    if (threadIdx.x == 0) sc = 0;
    __syncthreads();
    int i = blockIdx.x * 256 + threadIdx.x;
    if (g_labels[i] == i) atomicAdd(&sc, 1);
    __syncthreads();
    if (threadIdx.x == 0 && sc)
        atomicAdd(&g_counts[(blockIdx.x * 256) >> 18], sc);
}

// ---------------- final scalar assembly ----------------
__global__ void k_final(float* __restrict__ out){
    if (threadIdx.x == 0 && blockIdx.x == 0){
        double conn = 0.0;
        for (int n = 0; n < NPH; n++){
            int p = g_counts[n], t = g_counts[n + NPH];
            if (t > 0) conn += fabs((double)p - (double)t);
        }
        conn /= ((double)NPH + 1e-8);

        const double LN2 = 0.6931471805599453;       // BCE(x=0)
        const double L1  = 0.3132616875182228;       // log1p(e^-1)
        double Ntot = (double)HB * CB * HH * WW;
        double n1  = (double)g_cx1;
        double n11 = (double)g_cx1y1;
        double nv  = (double)g_cvalid;
        double bsum = LN2*(Ntot - n1) + (1.0 + L1)*(n1 - n11) + L1*n11;
        double bl = bsum / (nv + 1e-8);

        out[0] = (float)(bl + 0.1 * conn);
    }
}

// ---------------- launcher ----------------
extern "C" void kernel_launch(void* const* d_in, const int* in_sizes, int n_in,
                              void* d_out, int out_size){
    const float* pred = (const float*)d_in[0];
    const void*  tgt  = d_in[1];

    cudaFuncSetAttribute(k_fused, cudaFuncAttributeMaxDynamicSharedMemorySize, SMEM_BYTES);

    k_init<<<1, 256>>>((const int*)tgt);

    dim3 grid(HH/TILE, WW/TILE, HB);   // 16 x 16 x 4
    k_fused<<<grid, 256, SMEM_BYTES>>>(pred, tgt);

    int nb = (NP * HW) / 256;          // 155648 blocks
    k_merge<<<nb, 256>>>();
    k_count<<<nb, 256>>>();

    k_final<<<1, 32>>>((float*)d_out);
}

// round 4
// speedup vs baseline: 1.8157x; 1.8157x over previous
#include <cuda_runtime.h>
#include <math.h>

// Problem shapes (fixed by the dataset)
#define HB 4
#define CB 19
#define HH 512
#define WW 512
#define HW (HH*WW)            // 262144 = 1<<18
#define NPH (HB*CB)           // 76 planes per mask set
#define NP (2*NPH)            // 152 total planes (pred + tgt)
#define TILE 32
#define HALOD 34
#define HSZ (HALOD*HALOD)     // 1156
#define SMEM_BYTES ((CB*HSZ + HSZ)*4)   // 92480 bytes

// ---------------- device scratch (static, no allocation) ----------------
__device__ int g_labels[NP*HW];          // union-find labels, ~160 MB
__device__ int g_pcnt[NP];               // active - links  == component count
__device__ unsigned int g_cx1;           // count(pred_b & valid)
__device__ unsigned int g_cx1y1;         // count(pred_b & tgt_b & valid)
__device__ unsigned int g_cvalid;        // count(valid) over B,H,W
__device__ int g_is64;                   // target dtype flag

// ---------------- init: zero counters + detect target dtype -------------
__global__ void k_init(const int* __restrict__ tgt32){
    int tid = threadIdx.x;
    // if target is int64 (little-endian), every odd 32-bit word is 0
    int nz = 0;
    for (int j = tid; j < 1024; j += blockDim.x)
        nz |= (tgt32[2*j + 1] != 0);
    int any = __syncthreads_or(nz);
    if (tid == 0){
        g_is64 = (any == 0);
        g_cx1 = 0u; g_cx1y1 = 0u; g_cvalid = 0u;
    }
    if (tid < NP) g_pcnt[tid] = 0;
}

// ---------------- fused softmax + boundary + mask + CCL init + active counts
__global__ void __launch_bounds__(256)
k_fused(const float* __restrict__ pred, const void* __restrict__ tgt){
    extern __shared__ float smem[];
    float* s  = smem;                       // [CB][HSZ] softmax values
    int*   ts = (int*)(smem + CB*HSZ);      // [HSZ] target labels (-1 = outside)
    __shared__ int s_act[2*CB];             // active-pixel counters (pred, tgt)

    const int b   = blockIdx.z;
    const int tx0 = blockIdx.x * TILE;
    const int ty0 = blockIdx.y * TILE;
    const int tid = threadIdx.x;
    const int is64 = g_is64;
    const long long* t64 = (const long long*)tgt;
    const int*       t32 = (const int*)tgt;

    if (tid < 2*CB) s_act[tid] = 0;

    // ---- phase 1: load halo tile, compute per-pixel softmax into smem ----
    for (int hp = tid; hp < HSZ; hp += 256){
        int hy = hp / HALOD;
        int hx = hp - hy * HALOD;
        int gx = tx0 + hx - 1, gy = ty0 + hy - 1;
        int t = -1;
        if (gx >= 0 && gx < WW && gy >= 0 && gy < HH){
            int pix = b*HW + gy*WW + gx;
            t = is64 ? (int)t64[pix] : t32[pix];
            const float* base = pred + (size_t)b*CB*HW + (size_t)gy*WW + gx;
            float v[CB];
            float m = -1e30f;
            #pragma unroll
            for (int c = 0; c < CB; c++){ v[c] = base[(size_t)c*HW]; m = fmaxf(m, v[c]); }
            float sum = 0.f;
            #pragma unroll
            for (int c = 0; c < CB; c++){ v[c] = expf(v[c] - m); sum += v[c]; }
            float inv = 1.f / sum;
            #pragma unroll
            for (int c = 0; c < CB; c++) s[c*HSZ + hp] = v[c] * inv;
        } else {
            #pragma unroll
            for (int c = 0; c < CB; c++) s[c*HSZ + hp] = 0.f;
        }
        ts[hp] = t;
    }
    __syncthreads();

    // ---- phase 2: boundary counts + mask label init + active counts ----
    unsigned cx1 = 0, cx11 = 0, cval = 0;
    const int lane = tid & 31;
    const int px  = tid & 31;
    const int py0 = tid >> 5;
    #pragma unroll
    for (int k = 0; k < 4; k++){
        int py = py0 + k*8;
        int gx = tx0 + px, gy = ty0 + py;
        int hc = (py+1)*HALOD + (px+1);
        int tc = ts[hc];
        bool valid = (tc != 255);
        cval += valid ? 1u : 0u;
        int n0 = ts[hc-HALOD-1], n1 = ts[hc-HALOD], n2 = ts[hc-HALOD+1];
        int n3 = ts[hc-1],                            n4 = ts[hc+1];
        int n5 = ts[hc+HALOD-1], n6 = ts[hc+HALOD],  n7 = ts[hc+HALOD+1];
        int pixoff = gy*WW + gx;
        int baseP  = b*CB*HW + pixoff;
        #pragma unroll
        for (int c = 0; c < CB; c++){
            const float* sc = s + c*HSZ;
            float ctr = sc[hc];
            float ns  = sc[hc-HALOD-1] + sc[hc-HALOD] + sc[hc-HALOD+1]
                      + sc[hc-1]       +                 sc[hc+1]
                      + sc[hc+HALOD-1] + sc[hc+HALOD] + sc[hc+HALOD+1];
            float lap = 8.f*ctr - ns;
            bool pb = fabsf(lap) > 0.1f;            // pred boundary
            int oc   = (tc == c) ? 1 : 0;           // one-hot (255/-1 never match)
            int osum = (n0==c)+(n1==c)+(n2==c)+(n3==c)+(n4==c)+(n5==c)+(n6==c)+(n7==c);
            bool tb = (8*oc != osum);               // tgt boundary (|int lap| > 0.1)
            bool x1 = pb && valid;
            cx1  += x1 ? 1u : 0u;
            cx11 += (x1 && tb) ? 1u : 0u;
            bool mp = (ctr > 0.5f) && valid;        // pred mask pixel
            int gi = baseP + c*HW;
            g_labels[gi] = mp ? gi : -1;
            int gi2 = gi + NPH*HW;
            g_labels[gi2] = oc ? gi2 : -1;
            // active-pixel counts via ballot
            unsigned bp = __ballot_sync(0xffffffffu, mp);
            unsigned bt = __ballot_sync(0xffffffffu, oc != 0);
            if (lane == 0){
                if (bp) atomicAdd(&s_act[c],      (int)__popc(bp));
                if (bt) atomicAdd(&s_act[CB + c], (int)__popc(bt));
            }
        }
    }
    // warp reduce + per-warp atomics
    #pragma unroll
    for (int o = 16; o > 0; o >>= 1){
        cx1  += __shfl_down_sync(0xffffffffu, cx1,  o);
        cx11 += __shfl_down_sync(0xffffffffu, cx11, o);
        cval += __shfl_down_sync(0xffffffffu, cval, o);
    }
    if (lane == 0){
        atomicAdd(&g_cx1,   cx1);
        atomicAdd(&g_cx1y1, cx11);
        atomicAdd(&g_cvalid, cval);
    }
    __syncthreads();
    if (tid < 2*CB){
        int v = s_act[tid];
        if (v){
            int c = (tid < CB) ? tid : (tid - CB);
            int plane = b*CB + c + ((tid < CB) ? 0 : NPH);
            atomicAdd(&g_pcnt[plane], v);
        }
    }
}

// ---------------- union-find merge (counts links) ----------------
__device__ __forceinline__ int find_root(int a){
    int p = g_labels[a];
    while (p != a){ a = p; p = g_labels[a]; }
    return a;
}

__device__ __forceinline__ int uf_merge(int i, int j){
    int a = find_root(i);
    int c = find_root(j);
    while (a != c){
        if (c < a){ int t = a; a = c; c = t; }   // a = min, c = max
        int old = atomicMin(&g_labels[c], a);
        if (old == c) return 1;                  // c was root; now linked -> 1 link
        c = old;                                 // keep merging (old < c)
    }
    return 0;
}

// Each thread handles 4 consecutive pixels (int4). Block = 1024 pixels, one plane.
__global__ void __launch_bounds__(256)
k_merge(){
    __shared__ int s_links;
    if (threadIdx.x == 0) s_links = 0;
    __syncthreads();

    int t  = blockIdx.x * 256 + threadIdx.x;
    int i0 = t * 4;
    int4 L = *(const int4*)&g_labels[i0];
    int links = 0;
    bool a0 = L.x >= 0, a1 = L.y >= 0, a2 = L.z >= 0, a3 = L.w >= 0;
    if (a0 | a1 | a2 | a3){
        // internal horizontal merges
        if (a1 && a0) links += uf_merge(i0+1, i0);
        if (a2 && a1) links += uf_merge(i0+2, i0+1);
        if (a3 && a2) links += uf_merge(i0+3, i0+2);
        // left edge of the quad
        int x0 = i0 & (WW - 1);
        if (a0 && x0 > 0 && g_labels[i0-1] >= 0) links += uf_merge(i0, i0-1);
        // vertical merges with row above
        int y = (i0 >> 9) & (HH - 1);
        if (y > 0){
            int4 U = *(const int4*)&g_labels[i0 - WW];
            if (a0 && U.x >= 0) links += uf_merge(i0,   i0  -WW);
            if (a1 && U.y >= 0) links += uf_merge(i0+1, i0+1-WW);
            if (a2 && U.z >= 0) links += uf_merge(i0+2, i0+2-WW);
            if (a3 && U.w >= 0) links += uf_merge(i0+3, i0+3-WW);
        }
    }
    if (links) atomicAdd(&s_links, links);
    __syncthreads();
    if (threadIdx.x == 0 && s_links)
        atomicSub(&g_pcnt[(blockIdx.x * 1024) >> 18], s_links);
}

// ---------------- final scalar assembly ----------------
__global__ void k_final(float* __restrict__ out){
    if (threadIdx.x == 0 && blockIdx.x == 0){
        double conn = 0.0;
        for (int n = 0; n < NPH; n++){
            int p = g_pcnt[n], t = g_pcnt[n + NPH];
            if (t > 0) conn += fabs((double)p - (double)t);
        }
        conn /= ((double)NPH + 1e-8);

        const double LN2 = 0.6931471805599453;       // BCE(x=0)
        const double L1  = 0.3132616875182228;       // log1p(e^-1)
        double Ntot = (double)HB * CB * HH * WW;
        double n1  = (double)g_cx1;
        double n11 = (double)g_cx1y1;
        double nv  = (double)g_cvalid;
        double bsum = LN2*(Ntot - n1) + (1.0 + L1)*(n1 - n11) + L1*n11;
        double bl = bsum / (nv + 1e-8);

        out[0] = (float)(bl + 0.1 * conn);
    }
}

// ---------------- launcher ----------------
extern "C" void kernel_launch(void* const* d_in, const int* in_sizes, int n_in,
                              void* d_out, int out_size){
    const float* pred = (const float*)d_in[0];
    const void*  tgt  = d_in[1];

    cudaFuncSetAttribute(k_fused, cudaFuncAttributeMaxDynamicSharedMemorySize, SMEM_BYTES);

    k_init<<<1, 256>>>((const int*)tgt);

    dim3 grid(HH/TILE, WW/TILE, HB);   // 16 x 16 x 4
    k_fused<<<grid, 256, SMEM_BYTES>>>(pred, tgt);

    int nb = (NP * HW) / 1024;         // 38912 blocks, 4 px/thread
    k_merge<<<nb, 256>>>();

    k_final<<<1, 32>>>((float*)d_out);
}

// round 5
// speedup vs baseline: 1.9415x; 1.0693x over previous
#include <cuda_runtime.h>
#include <math.h>

// Problem shapes (fixed by the dataset)
#define HB 4
#define CB 19
#define HH 512
#define WW 512
#define HW (HH*WW)            // 262144 = 1<<18
#define NPH (HB*CB)           // 76 planes per mask set
#define NP (2*NPH)            // 152 total planes (pred + tgt)
#define TILE 32
#define HALOD 34
#define HSZ (HALOD*HALOD)     // 1156
#define SMEM_BYTES ((CB*HSZ + HSZ)*4)   // 92480 bytes

#define SROWS 32                       // rows per CCL strip
#define SPX   (WW*SROWS)               // 16384 px per strip
#define NSTRIP (HH/SROWS)              // 16 strips per plane
#define WPP  (HW/32)                   // 8192 words per plane
#define SMEM_CCL (SPX*4 + (SPX/32)*4)  // 64KB labels + 2KB bits

// ---------------- device scratch (static, no allocation) ----------------
__device__ int g_labels[NP*HW];          // global UF nodes (sparse use)
__device__ unsigned g_bits[NP*WPP];      // mask bitmaps, 5 MB
__device__ int g_bnd[NP*NSTRIP*2*WW];    // boundary-row local roots, 10 MB
__device__ int g_pcnt[NP];               // component count per plane
__device__ unsigned int g_cx1;           // count(pred_b & valid)
__device__ unsigned int g_cx1y1;         // count(pred_b & tgt_b & valid)
__device__ unsigned int g_cvalid;        // count(valid)
__device__ int g_is64;                   // target dtype flag

// ---------------- init ----------------
__global__ void k_init(const int* __restrict__ tgt32){
    int tid = threadIdx.x;
    int nz = 0;
    for (int j = tid; j < 1024; j += blockDim.x)
        nz |= (tgt32[2*j + 1] != 0);
    int any = __syncthreads_or(nz);
    if (tid == 0){
        g_is64 = (any == 0);
        g_cx1 = 0u; g_cx1y1 = 0u; g_cvalid = 0u;
    }
    if (tid < NP) g_pcnt[tid] = 0;
}

// ---------------- fused softmax + boundary + mask bitmaps ------------
__global__ void __launch_bounds__(256)
k_fused(const float* __restrict__ pred, const void* __restrict__ tgt){
    extern __shared__ float smem[];
    float* s  = smem;                       // [CB][HSZ] softmax values
    int*   ts = (int*)(smem + CB*HSZ);      // [HSZ] target labels

    const int b   = blockIdx.z;
    const int tx0 = blockIdx.x * TILE;
    const int ty0 = blockIdx.y * TILE;
    const int tid = threadIdx.x;
    const int is64 = g_is64;
    const long long* t64 = (const long long*)tgt;
    const int*       t32 = (const int*)tgt;

    // ---- phase 1: halo softmax ----
    for (int hp = tid; hp < HSZ; hp += 256){
        int hy = hp / HALOD;
        int hx = hp - hy * HALOD;
        int gx = tx0 + hx - 1, gy = ty0 + hy - 1;
        int t = -1;
        if (gx >= 0 && gx < WW && gy >= 0 && gy < HH){
            int pix = b*HW + gy*WW + gx;
            t = is64 ? (int)t64[pix] : t32[pix];
            const float* base = pred + (size_t)b*CB*HW + (size_t)gy*WW + gx;
            float v[CB];
            float m = -1e30f;
            #pragma unroll
            for (int c = 0; c < CB; c++){ v[c] = base[(size_t)c*HW]; m = fmaxf(m, v[c]); }
            float sum = 0.f;
            #pragma unroll
            for (int c = 0; c < CB; c++){ v[c] = expf(v[c] - m); sum += v[c]; }
            float inv = 1.f / sum;
            #pragma unroll
            for (int c = 0; c < CB; c++) s[c*HSZ + hp] = v[c] * inv;
        } else {
            #pragma unroll
            for (int c = 0; c < CB; c++) s[c*HSZ + hp] = 0.f;
        }
        ts[hp] = t;
    }
    __syncthreads();

    // ---- phase 2: boundary counts + bitmap stores ----
    unsigned cx1 = 0, cx11 = 0, cval = 0;
    const int lane = tid & 31;
    const int px  = tid & 31;
    const int py0 = tid >> 5;
    #pragma unroll
    for (int k = 0; k < 4; k++){
        int py = py0 + k*8;
        int gy = ty0 + py;
        int hc = (py+1)*HALOD + (px+1);
        int tc = ts[hc];
        bool valid = (tc != 255);
        cval += valid ? 1u : 0u;
        int n0 = ts[hc-HALOD-1], n1 = ts[hc-HALOD], n2 = ts[hc-HALOD+1];
        int n3 = ts[hc-1],                            n4 = ts[hc+1];
        int n5 = ts[hc+HALOD-1], n6 = ts[hc+HALOD],  n7 = ts[hc+HALOD+1];
        int wy = gy*16 + (tx0 >> 5);       // word index within plane
        #pragma unroll
        for (int c = 0; c < CB; c++){
            const float* sc = s + c*HSZ;
            float ctr = sc[hc];
            float ns  = sc[hc-HALOD-1] + sc[hc-HALOD] + sc[hc-HALOD+1]
                      + sc[hc-1]       +                 sc[hc+1]
                      + sc[hc+HALOD-1] + sc[hc+HALOD] + sc[hc+HALOD+1];
            float lap = 8.f*ctr - ns;
            bool pb = fabsf(lap) > 0.1f;            // pred boundary
            int oc   = (tc == c) ? 1 : 0;           // one-hot
            int osum = (n0==c)+(n1==c)+(n2==c)+(n3==c)+(n4==c)+(n5==c)+(n6==c)+(n7==c);
            bool tb = (8*oc != osum);               // tgt boundary
            bool x1 = pb && valid;
            cx1  += x1 ? 1u : 0u;
            cx11 += (x1 && tb) ? 1u : 0u;
            bool mp = (ctr > 0.5f) && valid;        // pred mask pixel
            unsigned bp = __ballot_sync(0xffffffffu, mp);
            unsigned bt = __ballot_sync(0xffffffffu, oc != 0);
            if (lane == 0){
                int w = (b*CB + c)*WPP + wy;
                g_bits[w] = bp;
                g_bits[w + NPH*WPP] = bt;
            }
        }
    }
    #pragma unroll
    for (int o = 16; o > 0; o >>= 1){
        cx1  += __shfl_down_sync(0xffffffffu, cx1,  o);
        cx11 += __shfl_down_sync(0xffffffffu, cx11, o);
        cval += __shfl_down_sync(0xffffffffu, cval, o);
    }
    if (lane == 0){
        atomicAdd(&g_cx1,   cx1);
        atomicAdd(&g_cx1y1, cx11);
        atomicAdd(&g_cvalid, cval);
    }
}

// ---------------- shared-memory union-find helpers ----------------
__device__ __forceinline__ int find_s(int* lab, int a){
    int p = lab[a];
    while (p != a){ a = p; p = lab[a]; }
    return a;
}
__device__ __forceinline__ int merge_s(int* lab, int i, int j){
    int a = find_s(lab, i);
    int c = find_s(lab, j);
    while (a != c){
        if (c < a){ int t = a; a = c; c = t; }
        int old = atomicMin(&lab[c], a);
        if (old == c) return 1;
        c = old;
    }
    return 0;
}

// ---------------- per-strip CCL in shared memory ----------------
__global__ void __launch_bounds__(256)
k_ccl(){
    extern __shared__ int sh[];
    int*      lab  = sh;                 // [SPX]
    unsigned* bits = (unsigned*)(sh + SPX); // [SPX/32] = 512 words
    __shared__ int s_links, s_act;

    const int plane = blockIdx.x >> 4;
    const int strip = blockIdx.x & (NSTRIP - 1);
    const int tid = threadIdx.x;
    if (tid == 0){ s_links = 0; s_act = 0; }

    // load strip bitmap (512 words)
    const int wbase = plane*WPP + strip*(SPX/32);
    for (int w = tid; w < SPX/32; w += 256)
        bits[w] = g_bits[wbase + w];

    // init labels
    for (int i0 = tid*4; i0 < SPX; i0 += 1024)
        *(int4*)&lab[i0] = make_int4(i0, i0+1, i0+2, i0+3);
    __syncthreads();

    // active count
    int act = 0;
    for (int w = tid; w < SPX/32; w += 256) act += __popc(bits[w]);

    // merge pass (left + up within strip)
    int links = 0;
    for (int i = tid; i < SPX; i += 256){
        if ((bits[i >> 5] >> (i & 31)) & 1u){
            int x = i & (WW - 1);
            if (x > 0 && ((bits[(i-1) >> 5] >> ((i-1) & 31)) & 1u))
                links += merge_s(lab, i, i - 1);
            if (i >= WW && ((bits[(i-WW) >> 5] >> ((i-WW) & 31)) & 1u))
                links += merge_s(lab, i, i - WW);
        }
    }
    #pragma unroll
    for (int o = 16; o > 0; o >>= 1){
        links += __shfl_down_sync(0xffffffffu, links, o);
        act   += __shfl_down_sync(0xffffffffu, act,   o);
    }
    if ((tid & 31) == 0){
        if (links) atomicAdd(&s_links, links);
        if (act)   atomicAdd(&s_act,   act);
    }
    __syncthreads();

    // export boundary-row roots + register global UF nodes
    const int nodebase = plane*HW + strip*SPX;
    const int bndbase  = (plane*NSTRIP + strip)*2*WW;
    for (int x = tid; x < WW; x += 256){
        // top row (local i = x)
        int rt = -1;
        if ((bits[x >> 5] >> (x & 31)) & 1u){
            rt = find_s(lab, x);
            g_labels[nodebase + rt] = nodebase + rt;
        }
        g_bnd[bndbase + x] = rt;
        // bottom row (local i = (SROWS-1)*WW + x)
        int ib = (SROWS-1)*WW + x;
        int rb = -1;
        if ((bits[ib >> 5] >> (ib & 31)) & 1u){
            rb = find_s(lab, ib);
            g_labels[nodebase + rb] = nodebase + rb;
        }
        g_bnd[bndbase + WW + x] = rb;
    }
    if (tid == 0 && (s_act | s_links))
        atomicAdd(&g_pcnt[plane], s_act - s_links);
}

// ---------------- global union-find across strip boundaries ----------------
__device__ __forceinline__ int find_g(int a){
    int p = g_labels[a];
    while (p != a){ a = p; p = g_labels[a]; }
    return a;
}
__device__ __forceinline__ int merge_g(int i, int j){
    int a = find_g(i);
    int c = find_g(j);
    while (a != c){
        if (c < a){ int t = a; a = c; c = t; }
        int old = atomicMin(&g_labels[c], a);
        if (old == c) return 1;
        c = old;
    }
    return 0;
}

__global__ void __launch_bounds__(256)
k_bmerge(){
    __shared__ int s_links;
    if (threadIdx.x == 0) s_links = 0;
    __syncthreads();

    const int plane = blockIdx.x / (NSTRIP - 1);
    const int s     = blockIdx.x % (NSTRIP - 1);
    const int botbase = (plane*NSTRIP + s)*2*WW + WW;       // bottom of strip s
    const int topbase = (plane*NSTRIP + s + 1)*2*WW;        // top of strip s+1
    int links = 0;
    for (int x = threadIdx.x; x < WW; x += 256){
        int rb = g_bnd[botbase + x];
        int rt = g_bnd[topbase + x];
        if (rb >= 0 && rt >= 0)
            links += merge_g(plane*HW + s*SPX + rb,
                             plane*HW + (s+1)*SPX + rt);
    }
    #pragma unroll
    for (int o = 16; o > 0; o >>= 1)
        links += __shfl_down_sync(0xffffffffu, links, o);
    if ((threadIdx.x & 31) == 0 && links) atomicAdd(&s_links, links);
    __syncthreads();
    if (threadIdx.x == 0 && s_links)
        atomicSub(&g_pcnt[plane], s_links);
}

// ---------------- final scalar assembly ----------------
__global__ void k_final(float* __restrict__ out){
    if (threadIdx.x == 0 && blockIdx.x == 0){
        double conn = 0.0;
        for (int n = 0; n < NPH; n++){
            int p = g_pcnt[n], t = g_pcnt[n + NPH];
            if (t > 0) conn += fabs((double)p - (double)t);
        }
        conn /= ((double)NPH + 1e-8);

        const double LN2 = 0.6931471805599453;       // BCE(x=0)
        const double L1  = 0.3132616875182228;       // log1p(e^-1)
        double Ntot = (double)HB * CB * HH * WW;
        double n1  = (double)g_cx1;
        double n11 = (double)g_cx1y1;
        double nv  = (double)g_cvalid;
        double bsum = LN2*(Ntot - n1) + (1.0 + L1)*(n1 - n11) + L1*n11;
        double bl = bsum / (nv + 1e-8);

        out[0] = (float)(bl + 0.1 * conn);
    }
}

// ---------------- launcher ----------------
extern "C" void kernel_launch(void* const* d_in, const int* in_sizes, int n_in,
                              void* d_out, int out_size){
    const float* pred = (const float*)d_in[0];
    const void*  tgt  = d_in[1];

    cudaFuncSetAttribute(k_fused, cudaFuncAttributeMaxDynamicSharedMemorySize, SMEM_BYTES);
    cudaFuncSetAttribute(k_ccl,   cudaFuncAttributeMaxDynamicSharedMemorySize, SMEM_CCL);

    k_init<<<1, 256>>>((const int*)tgt);

    dim3 grid(HH/TILE, WW/TILE, HB);   // 16 x 16 x 4
    k_fused<<<grid, 256, SMEM_BYTES>>>(pred, tgt);

    k_ccl<<<NP*NSTRIP, 256, SMEM_CCL>>>();         // 2432 blocks
    k_bmerge<<<NP*(NSTRIP-1), 256>>>();            // 2280 blocks

    k_final<<<1, 32>>>((float*)d_out);
}